// round 14
// baseline (speedup 1.0000x reference)
#include <cuda_runtime.h>
#include <math.h>

#define NN   50000
#define NE   800000
#define DIM  128
#define HID  128
#define ODIM 64
#define NL   3
#define NPB  8    // nodes per block (final kernel)
#define NPC  16   // nodes per block (input/combine; 50000 % 16 == 0)
#define SCAN_T 1024

// Scratch (no allocation allowed). Ping-pong feature buffers.
__device__ float g_h0[(size_t)NN * HID];
__device__ float g_h1[(size_t)NN * HID];
__device__ int   g_deg[NN];
__device__ int   g_off[NN + 1];
__device__ int   g_cur[NN];
__device__ int   g_esrc[NE];

__device__ __forceinline__ float gelu_f(float x) {
    return 0.5f * x * (1.0f + erff(x * 0.70710678118654752440f));
}

// ---------------------------------------------------------------------------
// In-degree count (int): one thread per edge
// ---------------------------------------------------------------------------
__global__ __launch_bounds__(256) void count_kernel(const int* __restrict__ dst) {
    int e = blockIdx.x * blockDim.x + threadIdx.x;
    if (e < NE) atomicAdd(&g_deg[dst[e]], 1);
}

// ---------------------------------------------------------------------------
// Exclusive prefix sum of g_deg -> g_off (and g_cur copy). One block.
// ---------------------------------------------------------------------------
__global__ __launch_bounds__(SCAN_T) void scan_kernel() {
    __shared__ int ssum[SCAN_T];
    int tid = threadIdx.x;
    const int CH = (NN + SCAN_T - 1) / SCAN_T;   // 49
    int base = tid * CH;

    int s = 0;
    for (int i = 0; i < CH; i++) {
        int idx = base + i;
        if (idx < NN) s += g_deg[idx];
    }
    ssum[tid] = s;
    __syncthreads();

    for (int off = 1; off < SCAN_T; off <<= 1) {
        int v = 0;
        if (tid >= off) v = ssum[tid - off];
        __syncthreads();
        if (tid >= off) ssum[tid] += v;
        __syncthreads();
    }

    int run = (tid == 0) ? 0 : ssum[tid - 1];
    for (int i = 0; i < CH; i++) {
        int idx = base + i;
        if (idx < NN) {
            g_off[idx] = run;
            g_cur[idx] = run;
            run += g_deg[idx];
        }
    }
    if (tid == SCAN_T - 1) g_off[NN] = run;
}

// ---------------------------------------------------------------------------
// Bucket-fill: g_esrc[pos] = src[e], grouped by dst
// ---------------------------------------------------------------------------
__global__ __launch_bounds__(256) void fill_kernel(
    const int* __restrict__ src, const int* __restrict__ dst)
{
    int e = blockIdx.x * blockDim.x + threadIdx.x;
    if (e >= NE) return;
    int d = dst[e];
    int pos = atomicAdd(&g_cur[d], 1);
    g_esrc[pos] = src[e];
}

// ---------------------------------------------------------------------------
// Fused: layernorm(x) -> @ in_proj + b -> gelu -> hout  (R13-proven)
// ---------------------------------------------------------------------------
__global__ __launch_bounds__(128) void input_kernel(
    const float* __restrict__ x,
    const float* __restrict__ lng, const float* __restrict__ lnb,
    const float* __restrict__ W,   const float* __restrict__ pb,
    float* __restrict__ hout)
{
    __shared__ __align__(16) float sm[NPC][DIM];
    int nb = blockIdx.x * NPC;
    int tid = threadIdx.x, w = tid >> 5, lane = tid & 31;

#pragma unroll
    for (int rr = 0; rr < 4; rr++) {
        int r = w + rr * 4;
        int node = nb + r;
        int c = lane * 4;
        float4 v = *(const float4*)(x + (size_t)node * DIM + c);
        float s  = v.x + v.y + v.z + v.w;
        float sq = v.x*v.x + v.y*v.y + v.z*v.z + v.w*v.w;
#pragma unroll
        for (int o = 16; o > 0; o >>= 1) {
            s  += __shfl_xor_sync(0xffffffffu, s,  o);
            sq += __shfl_xor_sync(0xffffffffu, sq, o);
        }
        float m    = s * (1.0f / DIM);
        float rstd = rsqrtf(sq * (1.0f / DIM) - m * m + 1e-5f);
        float4 o4;
        o4.x = (v.x - m) * rstd * lng[c + 0] + lnb[c + 0];
        o4.y = (v.y - m) * rstd * lng[c + 1] + lnb[c + 1];
        o4.z = (v.z - m) * rstd * lng[c + 2] + lnb[c + 2];
        o4.w = (v.w - m) * rstd * lng[c + 3] + lnb[c + 3];
        *(float4*)&sm[r][c] = o4;
    }
    __syncthreads();

    int cp    = (tid & 31) * 4;
    int rbase = (tid >> 5) * 4;

    float acc[4][4];
#pragma unroll
    for (int r = 0; r < 4; r++)
#pragma unroll
        for (int cc = 0; cc < 4; cc++) acc[r][cc] = 0.f;

#pragma unroll 4
    for (int k = 0; k < DIM; k += 4) {
        float4 w0 = *(const float4*)(W + (size_t)(k + 0) * HID + cp);
        float4 w1 = *(const float4*)(W + (size_t)(k + 1) * HID + cp);
        float4 w2 = *(const float4*)(W + (size_t)(k + 2) * HID + cp);
        float4 w3 = *(const float4*)(W + (size_t)(k + 3) * HID + cp);
#pragma unroll
        for (int r = 0; r < 4; r++) {
            float4 hv = *(const float4*)&sm[rbase + r][k];
            acc[r][0] += hv.x * w0.x + hv.y * w1.x + hv.z * w2.x + hv.w * w3.x;
            acc[r][1] += hv.x * w0.y + hv.y * w1.y + hv.z * w2.y + hv.w * w3.y;
            acc[r][2] += hv.x * w0.z + hv.y * w1.z + hv.z * w2.z + hv.w * w3.z;
            acc[r][3] += hv.x * w0.w + hv.y * w1.w + hv.z * w2.w + hv.w * w3.w;
        }
    }

    float4 bb = *(const float4*)(pb + cp);
#pragma unroll
    for (int r = 0; r < 4; r++) {
        int node = nb + rbase + r;
        float4 o4;
        o4.x = gelu_f(acc[r][0] + bb.x);
        o4.y = gelu_f(acc[r][1] + bb.y);
        o4.z = gelu_f(acc[r][2] + bb.z);
        o4.w = gelu_f(acc[r][3] + bb.w);
        *(float4*)(hout + (size_t)node * HID + cp) = o4;
    }
}

// ---------------------------------------------------------------------------
// Fused SAGE layer, ping-pong: reads hin ONLY, writes hout ONLY.
// Phase 1 gather unrolled x4 (MLP=4). Phase 2 split into two sequential
// passes (Wl then Wr) -> only 4 weight float4s live -> regs ~60, occ ~45%.
// ---------------------------------------------------------------------------
__global__ __launch_bounds__(128) void combine_kernel(
    const float* __restrict__ hin, float* __restrict__ hout,
    const float* __restrict__ Wl,  const float* __restrict__ bl,
    const float* __restrict__ Wr,
    const float* __restrict__ ng,  const float* __restrict__ nbeta)
{
    __shared__ __align__(16) float sm_m[NPC][DIM];
    __shared__ __align__(16) float sm_r[NPC][DIM];
    int nb = blockIdx.x * NPC;
    int tid = threadIdx.x, w = tid >> 5, lane = tid & 31;
    int c = lane * 4;

    // Phase 1: per warp, 4 nodes: CSR gather (unroll 4) -> mean; root row
#pragma unroll
    for (int rr = 0; rr < 4; rr++) {
        int r = w + rr * 4;
        int node = nb + r;

        int beg = __ldg(&g_off[node]);
        int end = __ldg(&g_off[node + 1]);

        float4 a0 = make_float4(0.f, 0.f, 0.f, 0.f);
        float4 a1 = make_float4(0.f, 0.f, 0.f, 0.f);
        float4 a2 = make_float4(0.f, 0.f, 0.f, 0.f);
        float4 a3 = make_float4(0.f, 0.f, 0.f, 0.f);
        int i = beg;
        for (; i + 4 <= end; i += 4) {
            int s0 = __ldg(&g_esrc[i]);
            int s1 = __ldg(&g_esrc[i + 1]);
            int s2 = __ldg(&g_esrc[i + 2]);
            int s3 = __ldg(&g_esrc[i + 3]);
            float4 v0 = *(const float4*)(hin + (size_t)s0 * HID + c);
            float4 v1 = *(const float4*)(hin + (size_t)s1 * HID + c);
            float4 v2 = *(const float4*)(hin + (size_t)s2 * HID + c);
            float4 v3 = *(const float4*)(hin + (size_t)s3 * HID + c);
            a0.x += v0.x; a0.y += v0.y; a0.z += v0.z; a0.w += v0.w;
            a1.x += v1.x; a1.y += v1.y; a1.z += v1.z; a1.w += v1.w;
            a2.x += v2.x; a2.y += v2.y; a2.z += v2.z; a2.w += v2.w;
            a3.x += v3.x; a3.y += v3.y; a3.z += v3.z; a3.w += v3.w;
        }
        for (; i < end; i++) {
            int s0 = __ldg(&g_esrc[i]);
            float4 v0 = *(const float4*)(hin + (size_t)s0 * HID + c);
            a0.x += v0.x; a0.y += v0.y; a0.z += v0.z; a0.w += v0.w;
        }
        float inv = 1.0f / (float)max(end - beg, 1);
        float4 m;
        m.x = (a0.x + a1.x + a2.x + a3.x) * inv;
        m.y = (a0.y + a1.y + a2.y + a3.y) * inv;
        m.z = (a0.z + a1.z + a2.z + a3.z) * inv;
        m.w = (a0.w + a1.w + a2.w + a3.w) * inv;
        *(float4*)&sm_m[r][c] = m;

        float4 h = *(const float4*)(hin + (size_t)node * HID + c);
        *(float4*)&sm_r[r][c] = h;
    }
    __syncthreads();

    // Phase 2: thread -> 4 cols x 4 rows; two sequential passes (low regs)
    int cp    = (tid & 31) * 4;
    int rbase = (tid >> 5) * 4;

    float acc[4][4];
#pragma unroll
    for (int r = 0; r < 4; r++)
#pragma unroll
        for (int cc = 0; cc < 4; cc++) acc[r][cc] = 0.f;

    // Pass A: mean @ Wl
#pragma unroll 4
    for (int k = 0; k < DIM; k += 4) {
        float4 w0 = *(const float4*)(Wl + (size_t)(k + 0) * HID + cp);
        float4 w1 = *(const float4*)(Wl + (size_t)(k + 1) * HID + cp);
        float4 w2 = *(const float4*)(Wl + (size_t)(k + 2) * HID + cp);
        float4 w3 = *(const float4*)(Wl + (size_t)(k + 3) * HID + cp);
#pragma unroll
        for (int r = 0; r < 4; r++) {
            float4 mv = *(const float4*)&sm_m[rbase + r][k];
            acc[r][0] += mv.x * w0.x + mv.y * w1.x + mv.z * w2.x + mv.w * w3.x;
            acc[r][1] += mv.x * w0.y + mv.y * w1.y + mv.z * w2.y + mv.w * w3.y;
            acc[r][2] += mv.x * w0.z + mv.y * w1.z + mv.z * w2.z + mv.w * w3.z;
            acc[r][3] += mv.x * w0.w + mv.y * w1.w + mv.z * w2.w + mv.w * w3.w;
        }
    }

    // Pass B: hin @ Wr
#pragma unroll 4
    for (int k = 0; k < DIM; k += 4) {
        float4 w0 = *(const float4*)(Wr + (size_t)(k + 0) * HID + cp);
        float4 w1 = *(const float4*)(Wr + (size_t)(k + 1) * HID + cp);
        float4 w2 = *(const float4*)(Wr + (size_t)(k + 2) * HID + cp);
        float4 w3 = *(const float4*)(Wr + (size_t)(k + 3) * HID + cp);
#pragma unroll
        for (int r = 0; r < 4; r++) {
            float4 hv = *(const float4*)&sm_r[rbase + r][k];
            acc[r][0] += hv.x * w0.x + hv.y * w1.x + hv.z * w2.x + hv.w * w3.x;
            acc[r][1] += hv.x * w0.y + hv.y * w1.y + hv.z * w2.y + hv.w * w3.y;
            acc[r][2] += hv.x * w0.z + hv.y * w1.z + hv.z * w2.z + hv.w * w3.z;
            acc[r][3] += hv.x * w0.w + hv.y * w1.w + hv.z * w2.w + hv.w * w3.w;
        }
    }
    __syncthreads();   // all reads of sm_m done before overwrite

    float4 bb = *(const float4*)(bl + cp);
#pragma unroll
    for (int r = 0; r < 4; r++) {
        float4 o4;
        o4.x = acc[r][0] + bb.x;
        o4.y = acc[r][1] + bb.y;
        o4.z = acc[r][2] + bb.z;
        o4.w = acc[r][3] + bb.w;
        *(float4*)&sm_m[rbase + r][cp] = o4;
    }
    __syncthreads();

    // Phase 3: per-row LN + gelu + residual -> hout (4 rows/warp)
#pragma unroll
    for (int rr = 0; rr < 4; rr++) {
        int r = w + rr * 4;
        int node = nb + r;
        float4 v = *(const float4*)&sm_m[r][c];
        float s  = v.x + v.y + v.z + v.w;
        float sq = v.x*v.x + v.y*v.y + v.z*v.z + v.w*v.w;
#pragma unroll
        for (int o = 16; o > 0; o >>= 1) {
            s  += __shfl_xor_sync(0xffffffffu, s,  o);
            sq += __shfl_xor_sync(0xffffffffu, sq, o);
        }
        float m    = s * (1.0f / HID);
        float rstd = rsqrtf(sq * (1.0f / HID) - m * m + 1e-5f);
        float4 hres = *(const float4*)&sm_r[r][c];
        float4 o4;
        o4.x = gelu_f((v.x - m) * rstd * ng[c + 0] + nbeta[c + 0]) + hres.x;
        o4.y = gelu_f((v.y - m) * rstd * ng[c + 1] + nbeta[c + 1]) + hres.y;
        o4.z = gelu_f((v.z - m) * rstd * ng[c + 2] + nbeta[c + 2]) + hres.z;
        o4.w = gelu_f((v.w - m) * rstd * ng[c + 3] + nbeta[c + 3]) + hres.w;
        *(float4*)(hout + (size_t)node * HID + c) = o4;
    }
}

// ---------------------------------------------------------------------------
// Fused: layernorm(hin) @ out_proj + b -> out.  (R9-proven, hin param)
// ---------------------------------------------------------------------------
__global__ __launch_bounds__(128) void final_kernel(
    const float* __restrict__ hin,
    const float* __restrict__ lng, const float* __restrict__ lnb,
    const float* __restrict__ W,   const float* __restrict__ pb,
    float* __restrict__ out)
{
    __shared__ __align__(16) float sm[NPB][DIM];
    int nb = blockIdx.x * NPB;
    int tid = threadIdx.x, w = tid >> 5, lane = tid & 31;

#pragma unroll
    for (int rr = 0; rr < 2; rr++) {
        int r = w + rr * 4;
        int node = nb + r;
        int c = lane * 4;
        float4 v = make_float4(0.f, 0.f, 0.f, 0.f);
        if (node < NN) v = *(const float4*)(hin + (size_t)node * HID + c);
        float s  = v.x + v.y + v.z + v.w;
        float sq = v.x*v.x + v.y*v.y + v.z*v.z + v.w*v.w;
#pragma unroll
        for (int o = 16; o > 0; o >>= 1) {
            s  += __shfl_xor_sync(0xffffffffu, s,  o);
            sq += __shfl_xor_sync(0xffffffffu, sq, o);
        }
        float m    = s * (1.0f / HID);
        float rstd = rsqrtf(sq * (1.0f / HID) - m * m + 1e-5f);
        float4 o4;
        o4.x = (v.x - m) * rstd * lng[c + 0] + lnb[c + 0];
        o4.y = (v.y - m) * rstd * lng[c + 1] + lnb[c + 1];
        o4.z = (v.z - m) * rstd * lng[c + 2] + lnb[c + 2];
        o4.w = (v.w - m) * rstd * lng[c + 3] + lnb[c + 3];
        *(float4*)&sm[r][c] = o4;
    }
    __syncthreads();

    int jj   = tid & 63;
    int half = tid >> 6;  // 0: rows 0-3, 1: rows 4-7
    float bias = pb[jj];
    float acc[4];
#pragma unroll
    for (int r = 0; r < 4; r++) acc[r] = bias;

#pragma unroll 4
    for (int k = 0; k < HID; k += 4) {
        float w0 = W[(k + 0) * ODIM + jj];
        float w1 = W[(k + 1) * ODIM + jj];
        float w2 = W[(k + 2) * ODIM + jj];
        float w3 = W[(k + 3) * ODIM + jj];
#pragma unroll
        for (int r = 0; r < 4; r++) {
            float4 hv = *(const float4*)&sm[half * 4 + r][k];
            acc[r] += hv.x * w0 + hv.y * w1 + hv.z * w2 + hv.w * w3;
        }
    }
#pragma unroll
    for (int r = 0; r < 4; r++) {
        int node = nb + half * 4 + r;
        if (node < NN) out[(size_t)node * ODIM + jj] = acc[r];
    }
}

// ---------------------------------------------------------------------------
extern "C" void kernel_launch(void* const* d_in, const int* in_sizes, int n_in,
                              void* d_out, int out_size)
{
    const float* x     = (const float*)d_in[0];
    const int*   ei    = (const int*)  d_in[1];
    const float* in_g  = (const float*)d_in[2];
    const float* in_b  = (const float*)d_in[3];
    const float* inW   = (const float*)d_in[4];
    const float* inPb  = (const float*)d_in[5];
    const float* Wl    = (const float*)d_in[6];
    const float* bl    = (const float*)d_in[7];
    const float* Wr    = (const float*)d_in[8];
    const float* ng    = (const float*)d_in[9];
    const float* nbta  = (const float*)d_in[10];
    const float* og    = (const float*)d_in[11];
    const float* ob    = (const float*)d_in[12];
    const float* oW    = (const float*)d_in[13];
    const float* oPb   = (const float*)d_in[14];
    float* out = (float*)d_out;

    const int* src = ei;
    const int* dst = ei + NE;

    void* degp = nullptr;
    void* h0p = nullptr;
    void* h1p = nullptr;
    cudaGetSymbolAddress(&degp, g_deg);
    cudaGetSymbolAddress(&h0p, g_h0);
    cudaGetSymbolAddress(&h1p, g_h1);
    float* buf[2] = { (float*)h0p, (float*)h1p };

    const int nblk  = (NN + NPB - 1) / NPB;          // 6250 (final)
    const int nblkc = NN / NPC;                      // 3125 (input/combine)

    // CSR build (per launch; graph-captured)
    cudaMemsetAsync(degp, 0, NN * sizeof(int));
    count_kernel<<<(NE + 255) / 256, 256>>>(dst);
    scan_kernel<<<1, SCAN_T>>>();
    fill_kernel<<<(NE + 255) / 256, 256>>>(src, dst);

    input_kernel<<<nblkc, 128>>>(x, in_g, in_b, inW, inPb, buf[0]);

    for (int l = 0; l < NL; l++) {
        combine_kernel<<<nblkc, 128>>>(buf[l & 1], buf[(l + 1) & 1],
                                       Wl + (size_t)l * HID * HID,
                                       bl + l * HID,
                                       Wr + (size_t)l * HID * HID,
                                       ng + l * HID,
                                       nbta + l * HID);
    }

    final_kernel<<<nblk, 128>>>(buf[NL & 1], og, ob, oW, oPb, out);
}

// round 15
// speedup vs baseline: 1.1060x; 1.1060x over previous
#include <cuda_runtime.h>
#include <math.h>

#define NN   50000
#define NE   800000
#define DIM  128
#define HID  128
#define ODIM 64
#define NL   3
#define NPB  8    // nodes per block (final kernel)
#define NPI  16   // nodes per block (input kernel; 50000 % 16 == 0)
#define NPC  32   // nodes per block (combine kernel; 50000 % 32 == 16 -> pad grid)
#define SCAN_T 1024

// Scratch (no allocation allowed). Ping-pong feature buffers.
__device__ float g_h0[(size_t)NN * HID];
__device__ float g_h1[(size_t)NN * HID];
__device__ int   g_deg[NN];
__device__ int   g_off[NN + 1];
__device__ int   g_cur[NN];
__device__ int   g_esrc[NE];

__device__ __forceinline__ float gelu_f(float x) {
    return 0.5f * x * (1.0f + erff(x * 0.70710678118654752440f));
}

// ---------------------------------------------------------------------------
// In-degree count (int): one thread per edge
// ---------------------------------------------------------------------------
__global__ __launch_bounds__(256) void count_kernel(const int* __restrict__ dst) {
    int e = blockIdx.x * blockDim.x + threadIdx.x;
    if (e < NE) atomicAdd(&g_deg[dst[e]], 1);
}

// ---------------------------------------------------------------------------
// Exclusive prefix sum of g_deg -> g_off (and g_cur copy). One block.
// ---------------------------------------------------------------------------
__global__ __launch_bounds__(SCAN_T) void scan_kernel() {
    __shared__ int ssum[SCAN_T];
    int tid = threadIdx.x;
    const int CH = (NN + SCAN_T - 1) / SCAN_T;   // 49
    int base = tid * CH;

    int s = 0;
    for (int i = 0; i < CH; i++) {
        int idx = base + i;
        if (idx < NN) s += g_deg[idx];
    }
    ssum[tid] = s;
    __syncthreads();

    for (int off = 1; off < SCAN_T; off <<= 1) {
        int v = 0;
        if (tid >= off) v = ssum[tid - off];
        __syncthreads();
        if (tid >= off) ssum[tid] += v;
        __syncthreads();
    }

    int run = (tid == 0) ? 0 : ssum[tid - 1];
    for (int i = 0; i < CH; i++) {
        int idx = base + i;
        if (idx < NN) {
            g_off[idx] = run;
            g_cur[idx] = run;
            run += g_deg[idx];
        }
    }
    if (tid == SCAN_T - 1) g_off[NN] = run;
}

// ---------------------------------------------------------------------------
// Bucket-fill: g_esrc[pos] = src[e], grouped by dst
// ---------------------------------------------------------------------------
__global__ __launch_bounds__(256) void fill_kernel(
    const int* __restrict__ src, const int* __restrict__ dst)
{
    int e = blockIdx.x * blockDim.x + threadIdx.x;
    if (e >= NE) return;
    int d = dst[e];
    int pos = atomicAdd(&g_cur[d], 1);
    g_esrc[pos] = src[e];
}

// ---------------------------------------------------------------------------
// Fused: layernorm(x) -> @ in_proj + b -> gelu -> hout  (R13-proven)
// ---------------------------------------------------------------------------
__global__ __launch_bounds__(128) void input_kernel(
    const float* __restrict__ x,
    const float* __restrict__ lng, const float* __restrict__ lnb,
    const float* __restrict__ W,   const float* __restrict__ pb,
    float* __restrict__ hout)
{
    __shared__ __align__(16) float sm[NPI][DIM];
    int nb = blockIdx.x * NPI;
    int tid = threadIdx.x, w = tid >> 5, lane = tid & 31;

#pragma unroll
    for (int rr = 0; rr < 4; rr++) {
        int r = w + rr * 4;
        int node = nb + r;
        int c = lane * 4;
        float4 v = *(const float4*)(x + (size_t)node * DIM + c);
        float s  = v.x + v.y + v.z + v.w;
        float sq = v.x*v.x + v.y*v.y + v.z*v.z + v.w*v.w;
#pragma unroll
        for (int o = 16; o > 0; o >>= 1) {
            s  += __shfl_xor_sync(0xffffffffu, s,  o);
            sq += __shfl_xor_sync(0xffffffffu, sq, o);
        }
        float m    = s * (1.0f / DIM);
        float rstd = rsqrtf(sq * (1.0f / DIM) - m * m + 1e-5f);
        float4 o4;
        o4.x = (v.x - m) * rstd * lng[c + 0] + lnb[c + 0];
        o4.y = (v.y - m) * rstd * lng[c + 1] + lnb[c + 1];
        o4.z = (v.z - m) * rstd * lng[c + 2] + lnb[c + 2];
        o4.w = (v.w - m) * rstd * lng[c + 3] + lnb[c + 3];
        *(float4*)&sm[r][c] = o4;
    }
    __syncthreads();

    int cp    = (tid & 31) * 4;
    int rbase = (tid >> 5) * 4;

    float acc[4][4];
#pragma unroll
    for (int r = 0; r < 4; r++)
#pragma unroll
        for (int cc = 0; cc < 4; cc++) acc[r][cc] = 0.f;

#pragma unroll 4
    for (int k = 0; k < DIM; k += 4) {
        float4 w0 = *(const float4*)(W + (size_t)(k + 0) * HID + cp);
        float4 w1 = *(const float4*)(W + (size_t)(k + 1) * HID + cp);
        float4 w2 = *(const float4*)(W + (size_t)(k + 2) * HID + cp);
        float4 w3 = *(const float4*)(W + (size_t)(k + 3) * HID + cp);
#pragma unroll
        for (int r = 0; r < 4; r++) {
            float4 hv = *(const float4*)&sm[rbase + r][k];
            acc[r][0] += hv.x * w0.x + hv.y * w1.x + hv.z * w2.x + hv.w * w3.x;
            acc[r][1] += hv.x * w0.y + hv.y * w1.y + hv.z * w2.y + hv.w * w3.y;
            acc[r][2] += hv.x * w0.z + hv.y * w1.z + hv.z * w2.z + hv.w * w3.z;
            acc[r][3] += hv.x * w0.w + hv.y * w1.w + hv.z * w2.w + hv.w * w3.w;
        }
    }

    float4 bb = *(const float4*)(pb + cp);
#pragma unroll
    for (int r = 0; r < 4; r++) {
        int node = nb + rbase + r;
        float4 o4;
        o4.x = gelu_f(acc[r][0] + bb.x);
        o4.y = gelu_f(acc[r][1] + bb.y);
        o4.z = gelu_f(acc[r][2] + bb.z);
        o4.w = gelu_f(acc[r][3] + bb.w);
        *(float4*)(hout + (size_t)node * HID + cp) = o4;
    }
}

// ---------------------------------------------------------------------------
// Fused SAGE layer, ping-pong (R13 structure), NPC=32 / 256 threads:
// halves per-layer weight re-reads (1563 blocks vs 3125).
// Phase 2: interleaved Wl/Wr, 4 cols x 4 rows per thread (R13-proven).
// Bounds checks on node (last block covers 49984..50015).
// ---------------------------------------------------------------------------
__global__ __launch_bounds__(256) void combine_kernel(
    const float* __restrict__ hin, float* __restrict__ hout,
    const float* __restrict__ Wl,  const float* __restrict__ bl,
    const float* __restrict__ Wr,
    const float* __restrict__ ng,  const float* __restrict__ nbeta)
{
    __shared__ __align__(16) float sm_m[NPC][DIM];
    __shared__ __align__(16) float sm_r[NPC][DIM];
    int nb = blockIdx.x * NPC;
    int tid = threadIdx.x, w = tid >> 5, lane = tid & 31;  // w: 0..7
    int c = lane * 4;

    // Phase 1: per warp, 4 nodes (rows w, w+8, w+16, w+24): gather -> mean
#pragma unroll
    for (int rr = 0; rr < 4; rr++) {
        int r = w + rr * 8;
        int node = nb + r;
        float4 m = make_float4(0.f, 0.f, 0.f, 0.f);
        float4 h = make_float4(0.f, 0.f, 0.f, 0.f);
        if (node < NN) {
            int beg = __ldg(&g_off[node]);
            int end = __ldg(&g_off[node + 1]);

            float4 a0 = make_float4(0.f, 0.f, 0.f, 0.f);
            float4 a1 = make_float4(0.f, 0.f, 0.f, 0.f);
            int i = beg;
            for (; i + 2 <= end; i += 2) {
                int s0 = __ldg(&g_esrc[i]);
                int s1 = __ldg(&g_esrc[i + 1]);
                float4 v0 = *(const float4*)(hin + (size_t)s0 * HID + c);
                float4 v1 = *(const float4*)(hin + (size_t)s1 * HID + c);
                a0.x += v0.x; a0.y += v0.y; a0.z += v0.z; a0.w += v0.w;
                a1.x += v1.x; a1.y += v1.y; a1.z += v1.z; a1.w += v1.w;
            }
            if (i < end) {
                int s0 = __ldg(&g_esrc[i]);
                float4 v0 = *(const float4*)(hin + (size_t)s0 * HID + c);
                a0.x += v0.x; a0.y += v0.y; a0.z += v0.z; a0.w += v0.w;
            }
            float inv = 1.0f / (float)max(end - beg, 1);
            m.x = (a0.x + a1.x) * inv;
            m.y = (a0.y + a1.y) * inv;
            m.z = (a0.z + a1.z) * inv;
            m.w = (a0.w + a1.w) * inv;
            h = *(const float4*)(hin + (size_t)node * HID + c);
        }
        *(float4*)&sm_m[r][c] = m;
        *(float4*)&sm_r[r][c] = h;
    }
    __syncthreads();

    // Phase 2: thread -> 4 cols (cp..cp+3) x 4 rows (rbase..+3), interleaved
    int cp    = (tid & 31) * 4;
    int rbase = (tid >> 5) * 4;   // 0,4,...,28

    float acc[4][4];
#pragma unroll
    for (int r = 0; r < 4; r++)
#pragma unroll
        for (int cc = 0; cc < 4; cc++) acc[r][cc] = 0.f;

#pragma unroll 4
    for (int k = 0; k < DIM; k += 4) {
        float4 wl0 = *(const float4*)(Wl + (size_t)(k + 0) * HID + cp);
        float4 wl1 = *(const float4*)(Wl + (size_t)(k + 1) * HID + cp);
        float4 wl2 = *(const float4*)(Wl + (size_t)(k + 2) * HID + cp);
        float4 wl3 = *(const float4*)(Wl + (size_t)(k + 3) * HID + cp);
        float4 wr0 = *(const float4*)(Wr + (size_t)(k + 0) * HID + cp);
        float4 wr1 = *(const float4*)(Wr + (size_t)(k + 1) * HID + cp);
        float4 wr2 = *(const float4*)(Wr + (size_t)(k + 2) * HID + cp);
        float4 wr3 = *(const float4*)(Wr + (size_t)(k + 3) * HID + cp);
#pragma unroll
        for (int r = 0; r < 4; r++) {
            float4 mv = *(const float4*)&sm_m[rbase + r][k];
            float4 hv = *(const float4*)&sm_r[rbase + r][k];
            acc[r][0] += mv.x * wl0.x + mv.y * wl1.x + mv.z * wl2.x + mv.w * wl3.x
                       + hv.x * wr0.x + hv.y * wr1.x + hv.z * wr2.x + hv.w * wr3.x;
            acc[r][1] += mv.x * wl0.y + mv.y * wl1.y + mv.z * wl2.y + mv.w * wl3.y
                       + hv.x * wr0.y + hv.y * wr1.y + hv.z * wr2.y + hv.w * wr3.y;
            acc[r][2] += mv.x * wl0.z + mv.y * wl1.z + mv.z * wl2.z + mv.w * wl3.z
                       + hv.x * wr0.z + hv.y * wr1.z + hv.z * wr2.z + hv.w * wr3.z;
            acc[r][3] += mv.x * wl0.w + mv.y * wl1.w + mv.z * wl2.w + mv.w * wl3.w
                       + hv.x * wr0.w + hv.y * wr1.w + hv.z * wr2.w + hv.w * wr3.w;
        }
    }
    __syncthreads();   // all reads of sm_m done before overwrite

    float4 bb = *(const float4*)(bl + cp);
#pragma unroll
    for (int r = 0; r < 4; r++) {
        float4 o4;
        o4.x = acc[r][0] + bb.x;
        o4.y = acc[r][1] + bb.y;
        o4.z = acc[r][2] + bb.z;
        o4.w = acc[r][3] + bb.w;
        *(float4*)&sm_m[rbase + r][cp] = o4;
    }
    __syncthreads();

    // Phase 3: per-row LN + gelu + residual -> hout (4 rows per warp)
#pragma unroll
    for (int rr = 0; rr < 4; rr++) {
        int r = w + rr * 8;
        int node = nb + r;
        float4 v = *(const float4*)&sm_m[r][c];
        float s  = v.x + v.y + v.z + v.w;
        float sq = v.x*v.x + v.y*v.y + v.z*v.z + v.w*v.w;
#pragma unroll
        for (int o = 16; o > 0; o >>= 1) {
            s  += __shfl_xor_sync(0xffffffffu, s,  o);
            sq += __shfl_xor_sync(0xffffffffu, sq, o);
        }
        float m    = s * (1.0f / HID);
        float rstd = rsqrtf(sq * (1.0f / HID) - m * m + 1e-5f);
        float4 hres = *(const float4*)&sm_r[r][c];
        float4 o4;
        o4.x = gelu_f((v.x - m) * rstd * ng[c + 0] + nbeta[c + 0]) + hres.x;
        o4.y = gelu_f((v.y - m) * rstd * ng[c + 1] + nbeta[c + 1]) + hres.y;
        o4.z = gelu_f((v.z - m) * rstd * ng[c + 2] + nbeta[c + 2]) + hres.z;
        o4.w = gelu_f((v.w - m) * rstd * ng[c + 3] + nbeta[c + 3]) + hres.w;
        if (node < NN) *(float4*)(hout + (size_t)node * HID + c) = o4;
    }
}

// ---------------------------------------------------------------------------
// Fused: layernorm(hin) @ out_proj + b -> out.  (R9-proven, hin param)
// ---------------------------------------------------------------------------
__global__ __launch_bounds__(128) void final_kernel(
    const float* __restrict__ hin,
    const float* __restrict__ lng, const float* __restrict__ lnb,
    const float* __restrict__ W,   const float* __restrict__ pb,
    float* __restrict__ out)
{
    __shared__ __align__(16) float sm[NPB][DIM];
    int nb = blockIdx.x * NPB;
    int tid = threadIdx.x, w = tid >> 5, lane = tid & 31;

#pragma unroll
    for (int rr = 0; rr < 2; rr++) {
        int r = w + rr * 4;
        int node = nb + r;
        int c = lane * 4;
        float4 v = make_float4(0.f, 0.f, 0.f, 0.f);
        if (node < NN) v = *(const float4*)(hin + (size_t)node * HID + c);
        float s  = v.x + v.y + v.z + v.w;
        float sq = v.x*v.x + v.y*v.y + v.z*v.z + v.w*v.w;
#pragma unroll
        for (int o = 16; o > 0; o >>= 1) {
            s  += __shfl_xor_sync(0xffffffffu, s,  o);
            sq += __shfl_xor_sync(0xffffffffu, sq, o);
        }
        float m    = s * (1.0f / HID);
        float rstd = rsqrtf(sq * (1.0f / HID) - m * m + 1e-5f);
        float4 o4;
        o4.x = (v.x - m) * rstd * lng[c + 0] + lnb[c + 0];
        o4.y = (v.y - m) * rstd * lng[c + 1] + lnb[c + 1];
        o4.z = (v.z - m) * rstd * lng[c + 2] + lnb[c + 2];
        o4.w = (v.w - m) * rstd * lng[c + 3] + lnb[c + 3];
        *(float4*)&sm[r][c] = o4;
    }
    __syncthreads();

    int jj   = tid & 63;
    int half = tid >> 6;  // 0: rows 0-3, 1: rows 4-7
    float bias = pb[jj];
    float acc[4];
#pragma unroll
    for (int r = 0; r < 4; r++) acc[r] = bias;

#pragma unroll 4
    for (int k = 0; k < HID; k += 4) {
        float w0 = W[(k + 0) * ODIM + jj];
        float w1 = W[(k + 1) * ODIM + jj];
        float w2 = W[(k + 2) * ODIM + jj];
        float w3 = W[(k + 3) * ODIM + jj];
#pragma unroll
        for (int r = 0; r < 4; r++) {
            float4 hv = *(const float4*)&sm[half * 4 + r][k];
            acc[r] += hv.x * w0 + hv.y * w1 + hv.z * w2 + hv.w * w3;
        }
    }
#pragma unroll
    for (int r = 0; r < 4; r++) {
        int node = nb + half * 4 + r;
        if (node < NN) out[(size_t)node * ODIM + jj] = acc[r];
    }
}

// ---------------------------------------------------------------------------
extern "C" void kernel_launch(void* const* d_in, const int* in_sizes, int n_in,
                              void* d_out, int out_size)
{
    const float* x     = (const float*)d_in[0];
    const int*   ei    = (const int*)  d_in[1];
    const float* in_g  = (const float*)d_in[2];
    const float* in_b  = (const float*)d_in[3];
    const float* inW   = (const float*)d_in[4];
    const float* inPb  = (const float*)d_in[5];
    const float* Wl    = (const float*)d_in[6];
    const float* bl    = (const float*)d_in[7];
    const float* Wr    = (const float*)d_in[8];
    const float* ng    = (const float*)d_in[9];
    const float* nbta  = (const float*)d_in[10];
    const float* og    = (const float*)d_in[11];
    const float* ob    = (const float*)d_in[12];
    const float* oW    = (const float*)d_in[13];
    const float* oPb   = (const float*)d_in[14];
    float* out = (float*)d_out;

    const int* src = ei;
    const int* dst = ei + NE;

    void* degp = nullptr;
    void* h0p = nullptr;
    void* h1p = nullptr;
    cudaGetSymbolAddress(&degp, g_deg);
    cudaGetSymbolAddress(&h0p, g_h0);
    cudaGetSymbolAddress(&h1p, g_h1);
    float* buf[2] = { (float*)h0p, (float*)h1p };

    const int nblk  = (NN + NPB - 1) / NPB;          // 6250 (final)
    const int nblki = NN / NPI;                      // 3125 (input)
    const int nblkc = (NN + NPC - 1) / NPC;          // 1563 (combine)

    // CSR build (per launch; graph-captured)
    cudaMemsetAsync(degp, 0, NN * sizeof(int));
    count_kernel<<<(NE + 255) / 256, 256>>>(dst);
    scan_kernel<<<1, SCAN_T>>>();
    fill_kernel<<<(NE + 255) / 256, 256>>>(src, dst);

    input_kernel<<<nblki, 128>>>(x, in_g, in_b, inW, inPb, buf[0]);

    for (int l = 0; l < NL; l++) {
        combine_kernel<<<nblkc, 256>>>(buf[l & 1], buf[(l + 1) & 1],
                                       Wl + (size_t)l * HID * HID,
                                       bl + l * HID,
                                       Wr + (size_t)l * HID * HID,
                                       ng + l * HID,
                                       nbta + l * HID);
    }

    final_kernel<<<nblk, 128>>>(buf[NL & 1], og, ob, oW, oPb, out);
}

// round 16
// speedup vs baseline: 1.2423x; 1.1232x over previous
#include <cuda_runtime.h>
#include <math.h>
#include <stdint.h>

#define NN   50000
#define NE   800000
#define DIM  128
#define HID  128
#define ODIM 64
#define NL   3
#define NPB  8    // nodes per block (final kernel)
#define NPC  16   // nodes per block (input/combine; == m16 tile height)
#define LDIM (DIM + 4)   // padded smem row stride (bank-conflict-free fragments)
#define SCAN_T 1024

// Scratch (no allocation allowed). Ping-pong feature buffers.
__device__ float g_h0[(size_t)NN * HID];
__device__ float g_h1[(size_t)NN * HID];
__device__ int   g_deg[NN];
__device__ int   g_off[NN + 1];
__device__ int   g_cur[NN];
__device__ int   g_esrc[NE];

__device__ __forceinline__ float gelu_f(float x) {
    return 0.5f * x * (1.0f + erff(x * 0.70710678118654752440f));
}

// ---- tf32 helpers (CUTLASS 3xTF32 split) ----------------------------------
__device__ __forceinline__ uint32_t tf32_rna(float x) {
    uint32_t r; asm("cvt.rna.tf32.f32 %0, %1;" : "=r"(r) : "f"(x)); return r;
}
__device__ __forceinline__ void tf32_split(float x, uint32_t& hi, uint32_t& lo) {
    hi = tf32_rna(x);
    lo = tf32_rna(x - __uint_as_float(hi));
}
__device__ __forceinline__ void mma_m16n8k8(float d[4], const uint32_t a[4],
                                            uint32_t b0, uint32_t b1) {
    asm("mma.sync.aligned.m16n8k8.row.col.f32.tf32.tf32.f32 "
        "{%0,%1,%2,%3}, {%4,%5,%6,%7}, {%8,%9}, {%0,%1,%2,%3};"
        : "+f"(d[0]), "+f"(d[1]), "+f"(d[2]), "+f"(d[3])
        : "r"(a[0]), "r"(a[1]), "r"(a[2]), "r"(a[3]), "r"(b0), "r"(b1));
}

// ---------------------------------------------------------------------------
// In-degree count (int): one thread per edge
// ---------------------------------------------------------------------------
__global__ __launch_bounds__(256) void count_kernel(const int* __restrict__ dst) {
    int e = blockIdx.x * blockDim.x + threadIdx.x;
    if (e < NE) atomicAdd(&g_deg[dst[e]], 1);
}

// ---------------------------------------------------------------------------
// Exclusive prefix sum of g_deg -> g_off (and g_cur copy). One block.
// ---------------------------------------------------------------------------
__global__ __launch_bounds__(SCAN_T) void scan_kernel() {
    __shared__ int ssum[SCAN_T];
    int tid = threadIdx.x;
    const int CH = (NN + SCAN_T - 1) / SCAN_T;   // 49
    int base = tid * CH;

    int s = 0;
    for (int i = 0; i < CH; i++) {
        int idx = base + i;
        if (idx < NN) s += g_deg[idx];
    }
    ssum[tid] = s;
    __syncthreads();

    for (int off = 1; off < SCAN_T; off <<= 1) {
        int v = 0;
        if (tid >= off) v = ssum[tid - off];
        __syncthreads();
        if (tid >= off) ssum[tid] += v;
        __syncthreads();
    }

    int run = (tid == 0) ? 0 : ssum[tid - 1];
    for (int i = 0; i < CH; i++) {
        int idx = base + i;
        if (idx < NN) {
            g_off[idx] = run;
            g_cur[idx] = run;
            run += g_deg[idx];
        }
    }
    if (tid == SCAN_T - 1) g_off[NN] = run;
}

// ---------------------------------------------------------------------------
// Bucket-fill: g_esrc[pos] = src[e], grouped by dst
// ---------------------------------------------------------------------------
__global__ __launch_bounds__(256) void fill_kernel(
    const int* __restrict__ src, const int* __restrict__ dst)
{
    int e = blockIdx.x * blockDim.x + threadIdx.x;
    if (e >= NE) return;
    int d = dst[e];
    int pos = atomicAdd(&g_cur[d], 1);
    g_esrc[pos] = src[e];
}

// ---------------------------------------------------------------------------
// Fused: layernorm(x) -> @ in_proj + b -> gelu -> hout
// Phase 2 on tensor cores: m16n8k8 tf32 x3 (fp32-accurate).
// ---------------------------------------------------------------------------
__global__ __launch_bounds__(128) void input_kernel(
    const float* __restrict__ x,
    const float* __restrict__ lng, const float* __restrict__ lnb,
    const float* __restrict__ W,   const float* __restrict__ pb,
    float* __restrict__ hout)
{
    __shared__ __align__(16) float sm[NPC][LDIM];
    int nb = blockIdx.x * NPC;
    int tid = threadIdx.x, w = tid >> 5, lane = tid & 31;

    // Phase 1: LN, 4 rows per warp
#pragma unroll
    for (int rr = 0; rr < 4; rr++) {
        int r = w + rr * 4;
        int node = nb + r;
        int c = lane * 4;
        float4 v = *(const float4*)(x + (size_t)node * DIM + c);
        float s  = v.x + v.y + v.z + v.w;
        float sq = v.x*v.x + v.y*v.y + v.z*v.z + v.w*v.w;
#pragma unroll
        for (int o = 16; o > 0; o >>= 1) {
            s  += __shfl_xor_sync(0xffffffffu, s,  o);
            sq += __shfl_xor_sync(0xffffffffu, sq, o);
        }
        float m    = s * (1.0f / DIM);
        float rstd = rsqrtf(sq * (1.0f / DIM) - m * m + 1e-5f);
        float4 o4;
        o4.x = (v.x - m) * rstd * lng[c + 0] + lnb[c + 0];
        o4.y = (v.y - m) * rstd * lng[c + 1] + lnb[c + 1];
        o4.z = (v.z - m) * rstd * lng[c + 2] + lnb[c + 2];
        o4.w = (v.w - m) * rstd * lng[c + 3] + lnb[c + 3];
        *(float4*)&sm[r][c] = o4;
    }
    __syncthreads();

    // Phase 2: TC matvec. Warp w -> cols [w*32, w*32+32).
    int gid = lane >> 2, tig = lane & 3;
    int n0w = w * 32;

    float d[4][4];
#pragma unroll
    for (int nt = 0; nt < 4; nt++)
#pragma unroll
        for (int i = 0; i < 4; i++) d[nt][i] = 0.f;

#pragma unroll 2
    for (int kt = 0; kt < 16; kt++) {
        int k0 = kt * 8;
        uint32_t ah[4], al[4];
        tf32_split(sm[gid    ][k0 + tig    ], ah[0], al[0]);
        tf32_split(sm[gid + 8][k0 + tig    ], ah[1], al[1]);
        tf32_split(sm[gid    ][k0 + tig + 4], ah[2], al[2]);
        tf32_split(sm[gid + 8][k0 + tig + 4], ah[3], al[3]);

#pragma unroll
        for (int nt = 0; nt < 4; nt++) {
            int n = n0w + nt * 8 + gid;
            float w0 = W[(size_t)(k0 + tig)     * HID + n];
            float w1 = W[(size_t)(k0 + tig + 4) * HID + n];
            uint32_t bh0, bl0, bh1, bl1;
            tf32_split(w0, bh0, bl0);
            tf32_split(w1, bh1, bl1);
            mma_m16n8k8(d[nt], ah, bh0, bh1);
            mma_m16n8k8(d[nt], al, bh0, bh1);
            mma_m16n8k8(d[nt], ah, bl0, bl1);
        }
    }

    // Epilogue: +bias, gelu, direct store (D frag: rows gid/gid+8, cols 2*tig)
#pragma unroll
    for (int nt = 0; nt < 4; nt++) {
        int col = n0w + nt * 8 + 2 * tig;
        float b0 = pb[col], b1 = pb[col + 1];
        int node0 = nb + gid;
        int node1 = nb + gid + 8;
        float2 o0, o1;
        o0.x = gelu_f(d[nt][0] + b0);
        o0.y = gelu_f(d[nt][1] + b1);
        o1.x = gelu_f(d[nt][2] + b0);
        o1.y = gelu_f(d[nt][3] + b1);
        *(float2*)(hout + (size_t)node0 * HID + col) = o0;
        *(float2*)(hout + (size_t)node1 * HID + col) = o1;
    }
}

// ---------------------------------------------------------------------------
// Fused SAGE layer, ping-pong: reads hin ONLY, writes hout ONLY.
// Phase 1: CSR gather (R13-proven, unroll 2). Phase 2: TC dual matvec
// (m16n8k8 tf32 x3). Phase 3: LN + gelu + residual.
// ---------------------------------------------------------------------------
__global__ __launch_bounds__(128) void combine_kernel(
    const float* __restrict__ hin, float* __restrict__ hout,
    const float* __restrict__ Wl,  const float* __restrict__ bias_l,
    const float* __restrict__ Wr,
    const float* __restrict__ ng,  const float* __restrict__ nbeta)
{
    __shared__ __align__(16) float sm_m[NPC][LDIM];
    __shared__ __align__(16) float sm_r[NPC][LDIM];
    int nb = blockIdx.x * NPC;
    int tid = threadIdx.x, w = tid >> 5, lane = tid & 31;
    int c = lane * 4;

    // Phase 1: per warp, 4 nodes: CSR gather -> mean; root row
#pragma unroll
    for (int rr = 0; rr < 4; rr++) {
        int r = w + rr * 4;
        int node = nb + r;

        int beg = __ldg(&g_off[node]);
        int end = __ldg(&g_off[node + 1]);

        float4 a0 = make_float4(0.f, 0.f, 0.f, 0.f);
        float4 a1 = make_float4(0.f, 0.f, 0.f, 0.f);
        int i = beg;
        for (; i + 2 <= end; i += 2) {
            int s0 = __ldg(&g_esrc[i]);
            int s1 = __ldg(&g_esrc[i + 1]);
            float4 v0 = *(const float4*)(hin + (size_t)s0 * HID + c);
            float4 v1 = *(const float4*)(hin + (size_t)s1 * HID + c);
            a0.x += v0.x; a0.y += v0.y; a0.z += v0.z; a0.w += v0.w;
            a1.x += v1.x; a1.y += v1.y; a1.z += v1.z; a1.w += v1.w;
        }
        if (i < end) {
            int s0 = __ldg(&g_esrc[i]);
            float4 v0 = *(const float4*)(hin + (size_t)s0 * HID + c);
            a0.x += v0.x; a0.y += v0.y; a0.z += v0.z; a0.w += v0.w;
        }
        float inv = 1.0f / (float)max(end - beg, 1);
        float4 m;
        m.x = (a0.x + a1.x) * inv;
        m.y = (a0.y + a1.y) * inv;
        m.z = (a0.z + a1.z) * inv;
        m.w = (a0.w + a1.w) * inv;
        *(float4*)&sm_m[r][c] = m;

        float4 h = *(const float4*)(hin + (size_t)node * HID + c);
        *(float4*)&sm_r[r][c] = h;
    }
    __syncthreads();

    // Phase 2: TC dual matvec. Warp w -> cols [w*32, w*32+32).
    int gid = lane >> 2, tig = lane & 3;
    int n0w = w * 32;

    float d[4][4];
#pragma unroll
    for (int nt = 0; nt < 4; nt++)
#pragma unroll
        for (int i = 0; i < 4; i++) d[nt][i] = 0.f;

#pragma unroll 2
    for (int kt = 0; kt < 16; kt++) {
        int k0 = kt * 8;
        uint32_t amh[4], aml[4], arh[4], arl[4];
        tf32_split(sm_m[gid    ][k0 + tig    ], amh[0], aml[0]);
        tf32_split(sm_m[gid + 8][k0 + tig    ], amh[1], aml[1]);
        tf32_split(sm_m[gid    ][k0 + tig + 4], amh[2], aml[2]);
        tf32_split(sm_m[gid + 8][k0 + tig + 4], amh[3], aml[3]);
        tf32_split(sm_r[gid    ][k0 + tig    ], arh[0], arl[0]);
        tf32_split(sm_r[gid + 8][k0 + tig    ], arh[1], arl[1]);
        tf32_split(sm_r[gid    ][k0 + tig + 4], arh[2], arl[2]);
        tf32_split(sm_r[gid + 8][k0 + tig + 4], arh[3], arl[3]);

#pragma unroll
        for (int nt = 0; nt < 4; nt++) {
            int n = n0w + nt * 8 + gid;
            {
                float w0 = Wl[(size_t)(k0 + tig)     * HID + n];
                float w1 = Wl[(size_t)(k0 + tig + 4) * HID + n];
                uint32_t bh0, bl0, bh1, bl1;
                tf32_split(w0, bh0, bl0);
                tf32_split(w1, bh1, bl1);
                mma_m16n8k8(d[nt], amh, bh0, bh1);
                mma_m16n8k8(d[nt], aml, bh0, bh1);
                mma_m16n8k8(d[nt], amh, bl0, bl1);
            }
            {
                float w0 = Wr[(size_t)(k0 + tig)     * HID + n];
                float w1 = Wr[(size_t)(k0 + tig + 4) * HID + n];
                uint32_t bh0, bl0, bh1, bl1;
                tf32_split(w0, bh0, bl0);
                tf32_split(w1, bh1, bl1);
                mma_m16n8k8(d[nt], arh, bh0, bh1);
                mma_m16n8k8(d[nt], arl, bh0, bh1);
                mma_m16n8k8(d[nt], arh, bl0, bl1);
            }
        }
    }
    __syncthreads();   // all reads of sm_m/sm_r done before overwriting sm_m

    // Store D (+bias) into sm_m
#pragma unroll
    for (int nt = 0; nt < 4; nt++) {
        int col = n0w + nt * 8 + 2 * tig;
        float b0 = bias_l[col], b1 = bias_l[col + 1];
        sm_m[gid    ][col]     = d[nt][0] + b0;
        sm_m[gid    ][col + 1] = d[nt][1] + b1;
        sm_m[gid + 8][col]     = d[nt][2] + b0;
        sm_m[gid + 8][col + 1] = d[nt][3] + b1;
    }
    __syncthreads();

    // Phase 3: per-row LN + gelu + residual -> hout (4 rows/warp)
#pragma unroll
    for (int rr = 0; rr < 4; rr++) {
        int r = w + rr * 4;
        int node = nb + r;
        float4 v = *(const float4*)&sm_m[r][c];
        float s  = v.x + v.y + v.z + v.w;
        float sq = v.x*v.x + v.y*v.y + v.z*v.z + v.w*v.w;
#pragma unroll
        for (int o = 16; o > 0; o >>= 1) {
            s  += __shfl_xor_sync(0xffffffffu, s,  o);
            sq += __shfl_xor_sync(0xffffffffu, sq, o);
        }
        float m    = s * (1.0f / HID);
        float rstd = rsqrtf(sq * (1.0f / HID) - m * m + 1e-5f);
        float4 hres = *(const float4*)&sm_r[r][c];
        float4 o4;
        o4.x = gelu_f((v.x - m) * rstd * ng[c + 0] + nbeta[c + 0]) + hres.x;
        o4.y = gelu_f((v.y - m) * rstd * ng[c + 1] + nbeta[c + 1]) + hres.y;
        o4.z = gelu_f((v.z - m) * rstd * ng[c + 2] + nbeta[c + 2]) + hres.z;
        o4.w = gelu_f((v.w - m) * rstd * ng[c + 3] + nbeta[c + 3]) + hres.w;
        *(float4*)(hout + (size_t)node * HID + c) = o4;
    }
}

// ---------------------------------------------------------------------------
// Fused: layernorm(hin) @ out_proj + b -> out.  (R9-proven, unchanged)
// ---------------------------------------------------------------------------
__global__ __launch_bounds__(128) void final_kernel(
    const float* __restrict__ hin,
    const float* __restrict__ lng, const float* __restrict__ lnb,
    const float* __restrict__ W,   const float* __restrict__ pb,
    float* __restrict__ out)
{
    __shared__ __align__(16) float sm[NPB][DIM];
    int nb = blockIdx.x * NPB;
    int tid = threadIdx.x, w = tid >> 5, lane = tid & 31;

#pragma unroll
    for (int rr = 0; rr < 2; rr++) {
        int r = w + rr * 4;
        int node = nb + r;
        int c = lane * 4;
        float4 v = make_float4(0.f, 0.f, 0.f, 0.f);
        if (node < NN) v = *(const float4*)(hin + (size_t)node * HID + c);
        float s  = v.x + v.y + v.z + v.w;
        float sq = v.x*v.x + v.y*v.y + v.z*v.z + v.w*v.w;
#pragma unroll
        for (int o = 16; o > 0; o >>= 1) {
            s  += __shfl_xor_sync(0xffffffffu, s,  o);
            sq += __shfl_xor_sync(0xffffffffu, sq, o);
        }
        float m    = s * (1.0f / HID);
        float rstd = rsqrtf(sq * (1.0f / HID) - m * m + 1e-5f);
        float4 o4;
        o4.x = (v.x - m) * rstd * lng[c + 0] + lnb[c + 0];
        o4.y = (v.y - m) * rstd * lng[c + 1] + lnb[c + 1];
        o4.z = (v.z - m) * rstd * lng[c + 2] + lnb[c + 2];
        o4.w = (v.w - m) * rstd * lng[c + 3] + lnb[c + 3];
        *(float4*)&sm[r][c] = o4;
    }
    __syncthreads();

    int jj   = tid & 63;
    int half = tid >> 6;  // 0: rows 0-3, 1: rows 4-7
    float bias = pb[jj];
    float acc[4];
#pragma unroll
    for (int r = 0; r < 4; r++) acc[r] = bias;

#pragma unroll 4
    for (int k = 0; k < HID; k += 4) {
        float w0 = W[(k + 0) * ODIM + jj];
        float w1 = W[(k + 1) * ODIM + jj];
        float w2 = W[(k + 2) * ODIM + jj];
        float w3 = W[(k + 3) * ODIM + jj];
#pragma unroll
        for (int r = 0; r < 4; r++) {
            float4 hv = *(const float4*)&sm[half * 4 + r][k];
            acc[r] += hv.x * w0 + hv.y * w1 + hv.z * w2 + hv.w * w3;
        }
    }
#pragma unroll
    for (int r = 0; r < 4; r++) {
        int node = nb + half * 4 + r;
        if (node < NN) out[(size_t)node * ODIM + jj] = acc[r];
    }
}

// ---------------------------------------------------------------------------
extern "C" void kernel_launch(void* const* d_in, const int* in_sizes, int n_in,
                              void* d_out, int out_size)
{
    const float* x     = (const float*)d_in[0];
    const int*   ei    = (const int*)  d_in[1];
    const float* in_g  = (const float*)d_in[2];
    const float* in_b  = (const float*)d_in[3];
    const float* inW   = (const float*)d_in[4];
    const float* inPb  = (const float*)d_in[5];
    const float* Wl    = (const float*)d_in[6];
    const float* bl    = (const float*)d_in[7];
    const float* Wr    = (const float*)d_in[8];
    const float* ng    = (const float*)d_in[9];
    const float* nbta  = (const float*)d_in[10];
    const float* og    = (const float*)d_in[11];
    const float* ob    = (const float*)d_in[12];
    const float* oW    = (const float*)d_in[13];
    const float* oPb   = (const float*)d_in[14];
    float* out = (float*)d_out;

    const int* src = ei;
    const int* dst = ei + NE;

    void* degp = nullptr;
    void* h0p = nullptr;
    void* h1p = nullptr;
    cudaGetSymbolAddress(&degp, g_deg);
    cudaGetSymbolAddress(&h0p, g_h0);
    cudaGetSymbolAddress(&h1p, g_h1);
    float* buf[2] = { (float*)h0p, (float*)h1p };

    const int nblk  = (NN + NPB - 1) / NPB;          // 6250 (final)
    const int nblkc = NN / NPC;                      // 3125 (input/combine)

    // CSR build (per launch; graph-captured)
    cudaMemsetAsync(degp, 0, NN * sizeof(int));
    count_kernel<<<(NE + 255) / 256, 256>>>(dst);
    scan_kernel<<<1, SCAN_T>>>();
    fill_kernel<<<(NE + 255) / 256, 256>>>(src, dst);

    input_kernel<<<nblkc, 128>>>(x, in_g, in_b, inW, inPb, buf[0]);

    for (int l = 0; l < NL; l++) {
        combine_kernel<<<nblkc, 128>>>(buf[l & 1], buf[(l + 1) & 1],
                                       Wl + (size_t)l * HID * HID,
                                       bl + l * HID,
                                       Wr + (size_t)l * HID * HID,
                                       ng + l * HID,
                                       nbta + l * HID);
    }

    final_kernel<<<nblk, 128>>>(buf[NL & 1], og, ob, oW, oPb, out);
}